// round 5
// baseline (speedup 1.0000x reference)
#include <cuda_runtime.h>
#include <cuda_bf16.h>
#include <math.h>
#include <stdint.h>

// Shapes (fixed)
#define D_HID 1024
#define SEQ   2048
#define BATCH 2
#define HEADS 16
#define HD    64
#define MROWS (BATCH*SEQ)                 // 4096
#define OUT_MAIN (MROWS*D_HID)            // 4194304
#define ATTN_ELEMS (MROWS*HEADS*HEADS)    // 1048576

// fp32 scratch
__device__ float g_q [MROWS*D_HID];
__device__ float g_k [MROWS*D_HID];
__device__ float g_v [MROWS*D_HID];
__device__ float g_cos[SEQ*(D_HID/2)];
__device__ float g_sin[SEQ*(D_HID/2)];

// bf16 split planes
__device__ __nv_bfloat16 g_in_h[MROWS*D_HID];
__device__ __nv_bfloat16 g_in_l[MROWS*D_HID];
__device__ __nv_bfloat16 g_cx_h[MROWS*D_HID];
__device__ __nv_bfloat16 g_cx_l[MROWS*D_HID];
__device__ __nv_bfloat16 g_xs_h[MROWS*D_HID];
__device__ __nv_bfloat16 g_xs_l[MROWS*D_HID];
__device__ __nv_bfloat16 g_wt_h[4*D_HID*D_HID];   // W^T hi, 4 weights
__device__ __nv_bfloat16 g_wt_l[4*D_HID*D_HID];   // W^T lo

__device__ __forceinline__ uint32_t smem_u32(const void* p) {
    uint32_t a;
    asm("{ .reg .u64 t; cvta.to.shared.u64 t, %1; cvt.u32.u64 %0, t; }"
        : "=r"(a) : "l"(p));
    return a;
}

// ---------------------------------------------------------------------------
// RoPE tables
// ---------------------------------------------------------------------------
__global__ void rope_tables_kernel() {
    int idx = blockIdx.x * blockDim.x + threadIdx.x;   // SEQ*512
    int s = idx >> 9;
    int j = idx & 511;
    float inv = expf(-(float)j * (9.210340371976184f / 512.0f));
    float arg = (float)s * inv;
    float sv, cv;
    sincosf(arg, &sv, &cv);
    g_cos[idx] = cv;
    g_sin[idx] = sv;
}

// ---------------------------------------------------------------------------
// fp32 -> bf16 hi/lo split for inputs (z=0) and context (z=1), vectorized
// ---------------------------------------------------------------------------
__global__ void conv_split2(const float4* __restrict__ s0,
                            const float4* __restrict__ s1, int n4)
{
    int idx = blockIdx.x * blockDim.x + threadIdx.x;
    if (idx >= n4) return;
    const float4* src = blockIdx.y ? s1 : s0;
    uint2* h = (uint2*)(blockIdx.y ? g_cx_h : g_in_h);
    uint2* l = (uint2*)(blockIdx.y ? g_cx_l : g_in_l);
    float4 v = src[idx];
    __nv_bfloat16 hx = __float2bfloat16_rn(v.x);
    __nv_bfloat16 hy = __float2bfloat16_rn(v.y);
    __nv_bfloat16 hz = __float2bfloat16_rn(v.z);
    __nv_bfloat16 hw = __float2bfloat16_rn(v.w);
    __nv_bfloat16 lx = __float2bfloat16_rn(v.x - __bfloat162float(hx));
    __nv_bfloat16 ly = __float2bfloat16_rn(v.y - __bfloat162float(hy));
    __nv_bfloat16 lz = __float2bfloat16_rn(v.z - __bfloat162float(hz));
    __nv_bfloat16 lw = __float2bfloat16_rn(v.w - __bfloat162float(hw));
    __nv_bfloat162 h01; h01.x = hx; h01.y = hy;
    __nv_bfloat162 h23; h23.x = hz; h23.y = hw;
    __nv_bfloat162 l01; l01.x = lx; l01.y = ly;
    __nv_bfloat162 l23; l23.x = lz; l23.y = lw;
    uint2 uh, ul;
    uh.x = *(uint32_t*)&h01; uh.y = *(uint32_t*)&h23;
    ul.x = *(uint32_t*)&l01; ul.y = *(uint32_t*)&l23;
    h[idx] = uh;
    l[idx] = ul;
}

// ---------------------------------------------------------------------------
// Weight transpose + split for all 4 weights (z selects), out at z*D*D
// ---------------------------------------------------------------------------
__global__ __launch_bounds__(256) void conv_wt4(const float* __restrict__ W0,
                                                const float* __restrict__ W1,
                                                const float* __restrict__ W2,
                                                const float* __restrict__ W3)
{
    __shared__ float t[32][33];
    int z = blockIdx.z;
    const float* W = (z == 0) ? W0 : (z == 1) ? W1 : (z == 2) ? W2 : W3;
    __nv_bfloat16* h = g_wt_h + (size_t)z * D_HID * D_HID;
    __nv_bfloat16* l = g_wt_l + (size_t)z * D_HID * D_HID;
    int x0 = blockIdx.x * 32;
    int y0 = blockIdx.y * 32;
    int tx = threadIdx.x, ty = threadIdx.y;   // (32,8)
    #pragma unroll
    for (int j = 0; j < 4; j++)
        t[ty + 8 * j][tx] = W[(size_t)(y0 + ty + 8 * j) * D_HID + x0 + tx];
    __syncthreads();
    #pragma unroll
    for (int j = 0; j < 4; j++) {
        int r = ty + 8 * j;
        float v = t[tx][r];
        __nv_bfloat16 hv = __float2bfloat16_rn(v);
        __nv_bfloat16 lv = __float2bfloat16_rn(v - __bfloat162float(hv));
        size_t o = (size_t)(x0 + r) * D_HID + y0 + tx;
        h[o] = hv;
        l[o] = lv;
    }
}

// ---------------------------------------------------------------------------
// bf16 3-term split GEMM: C[M,N] = A @ W + bias
//   CTA tile 256x128, 8 warps of 64x64, K-chunk 32, 4-stage cp.async.
//   MMA terms issued term-major (hh pass, hl pass, lh pass) so each
//   accumulator's RAW reuse distance is 32 MMAs -> full tensor-pipe rate.
// ---------------------------------------------------------------------------
#define KC 32
#define NSTAGE 4
#define PLANE_A 16384                    // 256 rows * 64B
#define PLANE_B 8192                     // 128 rows * 64B
#define STAGE_BYTES (2*PLANE_A + 2*PLANE_B)  // 49152
#define GEMM_SMEM (NSTAGE*STAGE_BYTES)       // 196608
#define NCHUNK (D_HID/KC)                // 32

#define LDSM4(r0,r1,r2,r3,addr) \
    asm volatile("ldmatrix.sync.aligned.m8n8.x4.shared.b16 {%0,%1,%2,%3}, [%4];" \
        : "=r"(r0), "=r"(r1), "=r"(r2), "=r"(r3) : "r"(addr))

#define MMA_BF16(d, a, b0v, b1v) \
    asm volatile("mma.sync.aligned.m16n8k16.row.col.f32.bf16.bf16.f32 " \
        "{%0,%1,%2,%3}, {%4,%5,%6,%7}, {%8,%9}, {%0,%1,%2,%3};" \
        : "+f"((d)[0]), "+f"((d)[1]), "+f"((d)[2]), "+f"((d)[3]) \
        : "r"((a)[0]), "r"((a)[1]), "r"((a)[2]), "r"((a)[3]), "r"(b0v), "r"(b1v))

__global__ __launch_bounds__(256, 1)
void gemm_bf16_split(const __nv_bfloat16* __restrict__ Ah,
                     const __nv_bfloat16* __restrict__ Al,
                     const __nv_bfloat16* __restrict__ Bh,
                     const __nv_bfloat16* __restrict__ Bl,
                     const float* __restrict__ bias, float* __restrict__ C)
{
    extern __shared__ char smem[];
    uint32_t sb = smem_u32(smem);
    int tid = threadIdx.x, lane = tid & 31, wid = tid >> 5;
    int wm = (wid & 3) * 64;        // warp M offset (4 warps over 256)
    int wn = (wid >> 2) * 64;       // warp N offset (2 warps over 128)

    int mbaseA = blockIdx.y * 256;
    int nbaseB = blockIdx.x * 128;

    // loader mapping
    int lrow = tid >> 1;            // 0..127
    int lb0  = (tid & 1) * 2;       // 16B block pair

    // ldmatrix lane address precompute
    uint32_t aOff[4]; int aSw[4];
    #pragma unroll
    for (int mt = 0; mt < 4; mt++) {
        int r = wm + mt * 16 + (lane & 7) + ((lane >> 3) & 1) * 8;
        aOff[mt] = r * 64;
        aSw[mt] = (r >> 1) & 3;
    }
    int g = lane >> 3;
    uint32_t bOff[4]; int bSw[4];
    #pragma unroll
    for (int pk = 0; pk < 4; pk++) {
        int r = wn + pk * 16 + ((g >> 1) << 3) + (lane & 7);
        bOff[pk] = r * 64;
        bSw[pk] = (r >> 1) & 3;
    }
    int aKb = lane >> 4;
    int bKb = g & 1;

    float acc[4][8][4];
    #pragma unroll
    for (int i = 0; i < 4; i++)
        #pragma unroll
        for (int j = 0; j < 8; j++)
            #pragma unroll
            for (int c = 0; c < 4; c++) acc[i][j][c] = 0.0f;

    #define LOAD_CHUNK(chunk, stage) do {                                        \
        uint32_t st0 = sb + (stage) * STAGE_BYTES;                               \
        int kk = (chunk) * KC;                                                   \
        _Pragma("unroll")                                                        \
        for (int rr = 0; rr < 2; rr++) {                                         \
            int r = lrow + rr * 128;                                             \
            int sw = (r >> 1) & 3;                                               \
            const __nv_bfloat16* sh = Ah + (size_t)(mbaseA + r) * D_HID + kk;    \
            const __nv_bfloat16* sl = Al + (size_t)(mbaseA + r) * D_HID + kk;    \
            _Pragma("unroll")                                                    \
            for (int j = 0; j < 2; j++) {                                        \
                int blk = lb0 + j;                                               \
                uint32_t d = st0 + r * 64 + ((blk ^ sw) << 4);                   \
                asm volatile("cp.async.cg.shared.global [%0], [%1], 16;"         \
                             :: "r"(d), "l"(sh + blk * 8));                      \
                asm volatile("cp.async.cg.shared.global [%0], [%1], 16;"         \
                             :: "r"(d + PLANE_A), "l"(sl + blk * 8));            \
            }                                                                    \
        }                                                                        \
        {                                                                        \
            int r = lrow;                                                        \
            int sw = (r >> 1) & 3;                                               \
            const __nv_bfloat16* sh = Bh + (size_t)(nbaseB + r) * D_HID + kk;    \
            const __nv_bfloat16* sl = Bl + (size_t)(nbaseB + r) * D_HID + kk;    \
            _Pragma("unroll")                                                    \
            for (int j = 0; j < 2; j++) {                                        \
                int blk = lb0 + j;                                               \
                uint32_t d = st0 + 2 * PLANE_A + r * 64 + ((blk ^ sw) << 4);     \
                asm volatile("cp.async.cg.shared.global [%0], [%1], 16;"         \
                             :: "r"(d), "l"(sh + blk * 8));                      \
                asm volatile("cp.async.cg.shared.global [%0], [%1], 16;"         \
                             :: "r"(d + PLANE_B), "l"(sl + blk * 8));            \
            }                                                                    \
        }                                                                        \
    } while (0)

    #pragma unroll
    for (int s = 0; s < NSTAGE - 1; s++) {
        LOAD_CHUNK(s, s);
        asm volatile("cp.async.commit_group;");
    }

    for (int i = 0; i < NCHUNK; i++) {
        asm volatile("cp.async.wait_group %0;" :: "n"(NSTAGE - 2));
        __syncthreads();

        if (i + NSTAGE - 1 < NCHUNK)
            LOAD_CHUNK(i + NSTAGE - 1, (i + NSTAGE - 1) & (NSTAGE - 1));
        asm volatile("cp.async.commit_group;");

        uint32_t st = sb + (i & (NSTAGE - 1)) * STAGE_BYTES;
        #pragma unroll
        for (int s = 0; s < 2; s++) {
            uint32_t bh[16], bl[16];
            #pragma unroll
            for (int pk = 0; pk < 4; pk++) {
                uint32_t ad = st + 2 * PLANE_A + bOff[pk]
                            + (((2 * s + bKb) ^ bSw[pk]) << 4);
                LDSM4(bh[pk*4+0], bh[pk*4+1], bh[pk*4+2], bh[pk*4+3], ad);
                LDSM4(bl[pk*4+0], bl[pk*4+1], bl[pk*4+2], bl[pk*4+3], ad + PLANE_B);
            }
            uint32_t ah[4][4], al[4][4];
            #pragma unroll
            for (int mt = 0; mt < 4; mt++) {
                uint32_t ad = st + aOff[mt] + (((2 * s + aKb) ^ aSw[mt]) << 4);
                LDSM4(ah[mt][0], ah[mt][1], ah[mt][2], ah[mt][3], ad);
                LDSM4(al[mt][0], al[mt][1], al[mt][2], al[mt][3], ad + PLANE_A);
            }
            // term-major passes: adjacent MMAs always hit different accumulators
            #pragma unroll
            for (int mt = 0; mt < 4; mt++)
                #pragma unroll
                for (int nt = 0; nt < 8; nt++)
                    MMA_BF16(acc[mt][nt], ah[mt], bh[nt*2], bh[nt*2+1]);
            #pragma unroll
            for (int mt = 0; mt < 4; mt++)
                #pragma unroll
                for (int nt = 0; nt < 8; nt++)
                    MMA_BF16(acc[mt][nt], ah[mt], bl[nt*2], bl[nt*2+1]);
            #pragma unroll
            for (int mt = 0; mt < 4; mt++)
                #pragma unroll
                for (int nt = 0; nt < 8; nt++)
                    MMA_BF16(acc[mt][nt], al[mt], bh[nt*2], bh[nt*2+1]);
        }
    }

    // epilogue
    #pragma unroll
    for (int mt = 0; mt < 4; mt++) {
        int row0 = blockIdx.y * 256 + wm + mt * 16 + (lane >> 2);
        #pragma unroll
        for (int nt = 0; nt < 8; nt++) {
            int col = blockIdx.x * 128 + wn + nt * 8 + (lane & 3) * 2;
            float b0 = bias[col], b1 = bias[col + 1];
            float2 v0, v1;
            v0.x = acc[mt][nt][0] + b0; v0.y = acc[mt][nt][1] + b1;
            v1.x = acc[mt][nt][2] + b0; v1.y = acc[mt][nt][3] + b1;
            *(float2*)(C + (size_t)row0 * D_HID + col) = v0;
            *(float2*)(C + (size_t)(row0 + 8) * D_HID + col) = v1;
        }
    }
}

// ---------------------------------------------------------------------------
// Fused: RoPE(q,k) + per-token head attention (16x16) + attn output +
// scrambled ctx written directly as bf16 hi/lo planes.
//   xs[b, h*128 + s/16, (s%16)*64 + d] = ctx[b, s, h, d]
// ---------------------------------------------------------------------------
__global__ __launch_bounds__(256) void attn_fused_kernel(float* __restrict__ attn_out,
                                                         int write_attn)
{
    __shared__ float sq[16][65];
    __shared__ float sk[16][65];
    __shared__ float sv[16][65];
    __shared__ float sc[16][17];

    int token = blockIdx.x;
    int tid   = threadIdx.x;
    int s     = token & (SEQ - 1);
    int b     = token >> 11;

    const float* qrow = g_q + (size_t)token * D_HID;
    const float* krow = g_k + (size_t)token * D_HID;
    const float* vrow = g_v + (size_t)token * D_HID;

    for (int i = tid; i < D_HID; i += 256) {
        int j  = i & 511;
        float c  = g_cos[(s << 9) | j];
        float sn = g_sin[(s << 9) | j];
        float qa = qrow[i], qb = qrow[i ^ 512];
        float ka = krow[i], kb = krow[i ^ 512];
        float rq, rk;
        if (i < 512) { rq = qa * c - qb * sn; rk = ka * c - kb * sn; }
        else         { rq = qa * c + qb * sn; rk = ka * c + kb * sn; }
        sq[i >> 6][i & 63] = rq;
        sk[i >> 6][i & 63] = rk;
        sv[i >> 6][i & 63] = vrow[i];
    }
    __syncthreads();

    {
        int h = tid >> 4, t = tid & 15;
        float acc = 0.0f;
        #pragma unroll
        for (int d = 0; d < HD; d++)
            acc = fmaf(sq[h][d], sk[t][d], acc);
        sc[h][t] = acc * 0.125f;
    }
    __syncthreads();

    if (tid < 16) {
        float m = -1e30f;
        #pragma unroll
        for (int t = 0; t < 16; t++) m = fmaxf(m, sc[tid][t]);
        float sum = 0.0f;
        #pragma unroll
        for (int t = 0; t < 16; t++) {
            float e = expf(sc[tid][t] - m);
            sc[tid][t] = e;
            sum += e;
        }
        float r = 1.0f / sum;
        #pragma unroll
        for (int t = 0; t < 16; t++) sc[tid][t] *= r;
    }
    __syncthreads();

    if (write_attn)
        attn_out[(size_t)token * 256 + tid] = sc[tid >> 4][tid & 15];

    // ctx + scrambled bf16 split write
    int o0 = tid * 4;
    int h  = o0 >> 6;
    int d0 = o0 & 63;
    size_t xbase = ((size_t)b * SEQ + (h * 128 + (s >> 4))) * D_HID
                 + ((s & 15) << 6);
    __nv_bfloat16* xh = g_xs_h + xbase;
    __nv_bfloat16* xl = g_xs_l + xbase;
    #pragma unroll
    for (int jj = 0; jj < 4; jj++) {
        int d = d0 + jj;
        float acc = 0.0f;
        #pragma unroll
        for (int t = 0; t < 16; t++)
            acc = fmaf(sc[h][t], sv[t][d], acc);
        __nv_bfloat16 hv = __float2bfloat16_rn(acc);
        __nv_bfloat16 lv = __float2bfloat16_rn(acc - __bfloat162float(hv));
        xh[d] = hv;
        xl[d] = lv;
    }
}

// ---------------------------------------------------------------------------
extern "C" void kernel_launch(void* const* d_in, const int* in_sizes, int n_in,
                              void* d_out, int out_size)
{
    const float* inputs  = (const float*)d_in[0];
    const float* context = (const float*)d_in[1];
    const float* Wq = (const float*)d_in[2];
    const float* bq = (const float*)d_in[3];
    const float* Wk = (const float*)d_in[4];
    const float* bk = (const float*)d_in[5];
    const float* Wv = (const float*)d_in[6];
    const float* bv = (const float*)d_in[7];
    const float* Wo = (const float*)d_in[8];
    const float* bo = (const float*)d_in[9];
    float* out = (float*)d_out;

    float *q, *k, *v;
    __nv_bfloat16 *inh, *inl, *cxh, *cxl, *xsh, *xsl, *wth, *wtl;
    cudaGetSymbolAddress((void**)&q,   g_q);
    cudaGetSymbolAddress((void**)&k,   g_k);
    cudaGetSymbolAddress((void**)&v,   g_v);
    cudaGetSymbolAddress((void**)&inh, g_in_h);
    cudaGetSymbolAddress((void**)&inl, g_in_l);
    cudaGetSymbolAddress((void**)&cxh, g_cx_h);
    cudaGetSymbolAddress((void**)&cxl, g_cx_l);
    cudaGetSymbolAddress((void**)&xsh, g_xs_h);
    cudaGetSymbolAddress((void**)&xsl, g_xs_l);
    cudaGetSymbolAddress((void**)&wth, g_wt_h);
    cudaGetSymbolAddress((void**)&wtl, g_wt_l);

    cudaFuncSetAttribute(gemm_bf16_split,
                         cudaFuncAttributeMaxDynamicSharedMemorySize, GEMM_SMEM);

    const size_t WSZ = (size_t)D_HID * D_HID;
    dim3 ggrid(D_HID / 128, MROWS / 256);   // (8, 16) = 128 CTAs
    int n4 = MROWS * D_HID / 4;

    // 1) tables + operand conversions (batched)
    rope_tables_kernel<<<(SEQ * 512) / 256, 256>>>();
    {
        dim3 cg((n4 + 255) / 256, 2);
        conv_split2<<<cg, 256>>>((const float4*)inputs, (const float4*)context, n4);
    }
    {
        dim3 wgrid(32, 32, 4), wblk(32, 8);
        conv_wt4<<<wgrid, wblk>>>(Wq, Wk, Wv, Wo);
    }

    // 2) q, k, v projections
    gemm_bf16_split<<<ggrid, 256, GEMM_SMEM>>>(inh, inl, wth + 0*WSZ, wtl + 0*WSZ, bq, q);
    gemm_bf16_split<<<ggrid, 256, GEMM_SMEM>>>(cxh, cxl, wth + 1*WSZ, wtl + 1*WSZ, bk, k);
    gemm_bf16_split<<<ggrid, 256, GEMM_SMEM>>>(cxh, cxl, wth + 2*WSZ, wtl + 2*WSZ, bv, v);

    // 3) fused RoPE + head-attention + scrambled bf16 ctx
    int write_attn = (out_size >= OUT_MAIN + ATTN_ELEMS) ? 1 : 0;
    attn_fused_kernel<<<MROWS, 256>>>(out + OUT_MAIN, write_attn);

    // 4) final projection
    gemm_bf16_split<<<ggrid, 256, GEMM_SMEM>>>(xsh, xsl, wth + 3*WSZ, wtl + 3*WSZ, bo, out);
}